// round 11
// baseline (speedup 1.0000x reference)
#include <cuda_runtime.h>

#define NT 1024

namespace {
constexpr int KSZ = 11;
constexpr int T = 64;
constexpr int IMG = 1024;
constexpr long long NPIX = 16LL * 1024 * 1024;

constexpr int RROWS = 84;      // T + 20
constexpr int RST   = 92;      // padded so 8-wide H groups can overread safely
constexpr int THROWS = 86;     // 84 + 2 pad rows for V overread
constexpr int MST   = 80;      // H-result / mu stride
constexpr int MRPAD  = 76;     // mu rows (74 + 2 pad)
constexpr int QST   = 64;

// shared layout (floats), all offsets mult of 4
constexpr int OFF_S1  = 0;                       // 84x92 = 7728
constexpr int OFF_S2  = OFF_S1  + RROWS * RST;   // 7728
constexpr int OFF_TH1 = OFF_S2  + RROWS * RST;   // 15456  (86x80)
constexpr int OFF_TH2 = OFF_TH1 + THROWS * MST;  // 22336  (86x80)
constexpr int OFF_TH3 = OFF_TH2 + THROWS * MST;  // 29216  (74x80, products only)
constexpr int OFF_M1  = OFF_TH3 + 74 * MST;      // 35136  (76x80)
constexpr int OFF_M2  = OFF_M1  + MRPAD * MST;   // 41216
constexpr int SMEM_FLOATS = OFF_M2 + MRPAD * MST;  // 47296 -> 189.2 KB

// reused regions
constexpr int OFF_Q1 = 0;                        // 74x64 in dead s region
constexpr int OFF_Q2 = OFF_Q1 + 74 * QST;        // 4736
constexpr int OFF_Q3 = OFF_Q2 + 74 * QST;        // 9472
constexpr int OFF_B1 = OFF_TH1;                  // 64x64 in dead tH region
constexpr int OFF_B2 = OFF_B1 + 64 * QST;
constexpr int OFF_B3 = OFF_B2 + 64 * QST;
}

__device__ int    g_min_bits = 0x7F800000;
__device__ int    g_max_bits = 0;
__device__ double g_sum = 0.0;

typedef unsigned long long ull;

__device__ __forceinline__ void ffma2(ull& d, ull a, ull b) {
    asm("fma.rn.f32x2 %0, %1, %2, %3;" : "=l"(d) : "l"(a), "l"(b), "l"(d));
}
union F2U { float2 f; ull u; };

// ---------------------------------------------------------------------------
__global__ void k_minmax(const float4* __restrict__ a, const float4* __restrict__ b, int n4) {
    float mn = __int_as_float(0x7F800000);
    float mx = 0.f;
    int stride = gridDim.x * blockDim.x;
    for (int i = blockIdx.x * blockDim.x + threadIdx.x; i < n4; i += stride) {
        float4 x = a[i], y = b[i];
        mn = fminf(mn, fminf(fminf(x.x, x.y), fminf(x.z, x.w)));
        mx = fmaxf(mx, fmaxf(fmaxf(x.x, x.y), fmaxf(x.z, x.w)));
        mn = fminf(mn, fminf(fminf(y.x, y.y), fminf(y.z, y.w)));
        mx = fmaxf(mx, fmaxf(fmaxf(y.x, y.y), fmaxf(y.z, y.w)));
    }
    #pragma unroll
    for (int o = 16; o; o >>= 1) {
        mn = fminf(mn, __shfl_xor_sync(0xFFFFFFFFu, mn, o));
        mx = fmaxf(mx, __shfl_xor_sync(0xFFFFFFFFu, mx, o));
    }
    if ((threadIdx.x & 31) == 0) {
        atomicMin(&g_min_bits, __float_as_int(mn));
        atomicMax(&g_max_bits, __float_as_int(mx));
    }
}

// ---------------------------------------------------------------------------
__global__ __launch_bounds__(NT, 1)
void k_ssim(const float* __restrict__ img1, const float* __restrict__ img2,
            const float* __restrict__ kern) {
    extern __shared__ float sm[];
    __shared__ float sw[12];
    __shared__ ull   sw2[12];
    __shared__ float red[NT / 32];

    const int tid = threadIdx.x;
    if (tid < KSZ) {
        float s = 0.f;
        #pragma unroll
        for (int j = 0; j < KSZ; j++) s += kern[tid * KSZ + j];
        sw[tid] = s;
        F2U u; u.f = make_float2(s, s);
        sw2[tid] = u.u;
    }

    const float mnv = __int_as_float(g_min_bits);
    const float mxv = __int_as_float(g_max_bits);
    const float vr = mxv - mnv + 1e-5f;
    float C1 = 0.01f * vr; C1 *= C1;
    float C2 = 0.03f * vr; C2 *= C2;

    const int bx = blockIdx.x, by = blockIdx.y, bz = blockIdx.z;
    const float* i1 = img1 + (size_t)bz * (IMG * IMG);
    const float* i2 = img2 + (size_t)bz * (IMG * IMG);
    const int y0 = by * T - 10;
    const int x0 = bx * T - 10;

    float* s1  = sm + OFF_S1;
    float* s2  = sm + OFF_S2;
    float* tH1 = sm + OFF_TH1;
    float* tH2 = sm + OFF_TH2;
    float* tH3 = sm + OFF_TH3;
    float* m1  = sm + OFF_M1;
    float* m2  = sm + OFF_M2;

    // ---- P0: load tiles (zero-pad outside the image) --------------------
    for (int i = tid; i < 2 * RROWS * RST; i += NT) {
        int img = i >= RROWS * RST;
        int t2 = i - img * RROWS * RST;
        int r = t2 / RST, c = t2 - r * RST;
        int gy = y0 + r, gx = x0 + c;
        bool in = (gy >= 0 && gy < IMG && gx >= 0 && gx < IMG);
        int gi = gy * IMG + gx;
        (img ? s2 : s1)[t2] = in ? (img ? i2 : i1)[gi] : 0.f;
    }
    __syncthreads();

    // ---- P1: H-blur both images, 8-wide groups (84 x 10 x 2 = 1680) -----
    for (int it = tid; it < 2 * RROWS * 10; it += NT) {
        int img = it >= RROWS * 10;
        int t2 = it - img * RROWS * 10;
        int row = t2 / 10, c8 = (t2 - row * 10) * 8;
        const float* src = (img ? s2 : s1) + row * RST + c8;
        float vf[20];
        #pragma unroll
        for (int q = 0; q < 5; q++) {
            float4 v = *(const float4*)(src + 4 * q);
            vf[4*q] = v.x; vf[4*q+1] = v.y; vf[4*q+2] = v.z; vf[4*q+3] = v.w;
        }
        float a[8];
        #pragma unroll
        for (int j = 0; j < 8; j++) a[j] = 0.f;
        #pragma unroll
        for (int k = 0; k < KSZ; k++) {
            float w = sw[k];
            #pragma unroll
            for (int j = 0; j < 8; j++) a[j] = fmaf(w, vf[k + j], a[j]);
        }
        float* dst = (img ? tH2 : tH1) + row * MST + c8;
        *(float4*)dst       = make_float4(a[0], a[1], a[2], a[3]);
        *(float4*)(dst + 4) = make_float4(a[4], a[5], a[6], a[7]);
    }
    __syncthreads();

    // ---- P2: V-blur -> mu, 4row x 4col streamed (19 x 19 x 2 = 722) -----
    for (int it = tid; it < 2 * 19 * 19; it += NT) {
        int img = it >= 19 * 19;
        int t2 = it - img * 19 * 19;
        int rg = t2 / 19, c4 = (t2 - rg * 19) * 4;
        int r4 = rg * 4;
        const float* src = (img ? tH2 : tH1) + r4 * MST + c4;
        ull acc[4][2];
        #pragma unroll
        for (int r = 0; r < 4; r++) { acc[r][0] = 0; acc[r][1] = 0; }
        #pragma unroll
        for (int k = 0; k < 14; k++) {
            ulonglong2 q = *(const ulonglong2*)(src + k * MST);
            #pragma unroll
            for (int r = 0; r < 4; r++) {
                int t = k - r;
                if (t >= 0 && t < KSZ) {
                    ull wk = sw2[t];
                    ffma2(acc[r][0], wk, q.x);
                    ffma2(acc[r][1], wk, q.y);
                }
            }
        }
        float* dst = (img ? m2 : m1) + r4 * MST + c4;
        #pragma unroll
        for (int r = 0; r < 4; r++)
            *(ulonglong2*)(dst + r * MST) = make_ulonglong2(acc[r][0], acc[r][1]);
    }
    __syncthreads();

    // ---- P3: products, zeroed outside image (74 x 74) -------------------
    {
        int my0 = y0 + 5, mx0 = x0 + 5;
        for (int i = tid; i < 74 * 74; i += NT) {
            int r = i / 74, c = i - r * 74;
            int gy = my0 + r, gx = mx0 + c;
            bool in = (gy >= 0 && gy < IMG && gx >= 0 && gx < IMG);
            int mi = r * MST + c;
            float d1 = s1[(r + 5) * RST + (c + 5)] - m1[mi];
            float d2 = s2[(r + 5) * RST + (c + 5)] - m2[mi];
            tH1[mi] = in ? d1 * d1 : 0.f;
            tH2[mi] = in ? d2 * d2 : 0.f;
            tH3[mi] = in ? d1 * d2 : 0.f;
        }
    }
    __syncthreads();

    // ---- P4: H-blur 3 products, 8-wide (74 x 8 x 3 = 1776) --------------
    for (int it = tid; it < 3 * 74 * 8; it += NT) {
        int p = it / (74 * 8);
        int t2 = it - p * (74 * 8);
        int row = t2 / 8, c8 = (t2 - row * 8) * 8;
        const float* src = (p == 0 ? tH1 : (p == 1 ? tH2 : tH3)) + row * MST + c8;
        float vf[20];
        #pragma unroll
        for (int q = 0; q < 5; q++) {
            float4 v = *(const float4*)(src + 4 * q);
            vf[4*q] = v.x; vf[4*q+1] = v.y; vf[4*q+2] = v.z; vf[4*q+3] = v.w;
        }
        float a[8];
        #pragma unroll
        for (int j = 0; j < 8; j++) a[j] = 0.f;
        #pragma unroll
        for (int k = 0; k < KSZ; k++) {
            float w = sw[k];
            #pragma unroll
            for (int j = 0; j < 8; j++) a[j] = fmaf(w, vf[k + j], a[j]);
        }
        float* dst = sm + (p == 0 ? OFF_Q1 : (p == 1 ? OFF_Q2 : OFF_Q3)) + row * QST + c8;
        *(float4*)dst       = make_float4(a[0], a[1], a[2], a[3]);
        *(float4*)(dst + 4) = make_float4(a[4], a[5], a[6], a[7]);
    }
    __syncthreads();

    // ---- P5a: V-blur 3 products, 4row x 4col (16 x 16 x 3 = 768) --------
    for (int it = tid; it < 3 * 16 * 16; it += NT) {
        int p = it / (16 * 16);
        int t2 = it - p * (16 * 16);
        int rg = t2 / 16, c4 = (t2 - rg * 16) * 4;
        int r4 = rg * 4;
        const float* src = sm + (p == 0 ? OFF_Q1 : (p == 1 ? OFF_Q2 : OFF_Q3))
                           + r4 * QST + c4;
        ull acc[4][2];
        #pragma unroll
        for (int r = 0; r < 4; r++) { acc[r][0] = 0; acc[r][1] = 0; }
        #pragma unroll
        for (int k = 0; k < 14; k++) {
            ulonglong2 q = *(const ulonglong2*)(src + k * QST);
            #pragma unroll
            for (int r = 0; r < 4; r++) {
                int t = k - r;
                if (t >= 0 && t < KSZ) {
                    ull wk = sw2[t];
                    ffma2(acc[r][0], wk, q.x);
                    ffma2(acc[r][1], wk, q.y);
                }
            }
        }
        float* dst = sm + (p == 0 ? OFF_B1 : (p == 1 ? OFF_B2 : OFF_B3)) + r4 * QST + c4;
        #pragma unroll
        for (int r = 0; r < 4; r++)
            *(ulonglong2*)(dst + r * QST) = make_ulonglong2(acc[r][0], acc[r][1]);
    }
    __syncthreads();

    // ---- P5b: combine + reduce (64 x 16 = 1024 items, 4 px each) --------
    float acc = 0.f;
    {
        int r = tid / 16, c4 = (tid - (tid / 16) * 16) * 4;
        float4 v11 = *(const float4*)(sm + OFF_B1 + r * QST + c4);
        float4 v22 = *(const float4*)(sm + OFF_B2 + r * QST + c4);
        float4 v12 = *(const float4*)(sm + OFF_B3 + r * QST + c4);
        const float* s11 = &v11.x;
        const float* s22 = &v22.x;
        const float* s12 = &v12.x;
        #pragma unroll
        for (int j = 0; j < 4; j++) {
            float u1 = m1[(r + 5) * MST + (c4 + 5 + j)];
            float u2 = m2[(r + 5) * MST + (c4 + 5 + j)];
            float a = s11[j] + 1.f;
            float b = s22[j] + 1.f;
            float c = s12[j] + 1.f;
            float m11 = u1 * u1 + 1.f;
            float m22 = u2 * u2 + 1.f;
            float m12 = u1 * u2 + 1.f;
            float t2v = 2.f * m12;
            float t1v = m11 + m22;
            float num = (2.f * c + C2) * (t2v * t2v + C1);
            float den = (a + b + C2) * (t1v * t1v + C1);
            acc += __fdividef(num, den);
        }
    }
    #pragma unroll
    for (int o = 16; o; o >>= 1) acc += __shfl_xor_sync(0xFFFFFFFFu, acc, o);
    if ((tid & 31) == 0) red[tid >> 5] = acc;
    __syncthreads();
    if (tid < 32) {
        float v = red[tid];   // NT/32 == 32 partials, one per lane
        #pragma unroll
        for (int o = 16; o; o >>= 1) v += __shfl_xor_sync(0xFFFFFFFFu, v, o);
        if (tid == 0) atomicAdd(&g_sum, (double)v);
    }
}

// ---------------------------------------------------------------------------
// finalize + reset accumulators for the next (graph-replayed) call
__global__ void k_final(float* __restrict__ out) {
    out[0] = 1.0f - (float)(g_sum * (1.0 / (double)NPIX));
    g_sum = 0.0;
    g_min_bits = 0x7F800000;
    g_max_bits = 0;
}

// ---------------------------------------------------------------------------
extern "C" void kernel_launch(void* const* d_in, const int* in_sizes, int n_in,
                              void* d_out, int out_size) {
    const float* img1 = (const float*)d_in[0];
    const float* img2 = (const float*)d_in[1];
    const float* kern = (const float*)d_in[2];
    float* out = (float*)d_out;

    cudaFuncSetAttribute(k_ssim, cudaFuncAttributeMaxDynamicSharedMemorySize,
                         SMEM_FLOATS * (int)sizeof(float));

    k_minmax<<<1024, 256>>>((const float4*)img1, (const float4*)img2,
                            (int)(NPIX / 4));
    dim3 grid(IMG / T, IMG / T, 16);
    k_ssim<<<grid, NT, SMEM_FLOATS * (int)sizeof(float)>>>(img1, img2, kern);
    k_final<<<1, 1>>>(out);
}

// round 15
// speedup vs baseline: 1.1531x; 1.1531x over previous
#include <cuda_runtime.h>

#define NT 512

namespace {
constexpr int KSZ = 11;
constexpr int T = 64;
constexpr int IMG = 1024;
constexpr long long NPIX = 16LL * 1024 * 1024;

constexpr int RROWS = 84;      // T + 20
constexpr int RST   = 92;      // raw stride (8-wide H groups overread safely)
constexpr int THROWS = 86;     // 84 + 2 pad rows for 4-row V overread
constexpr int MST   = 80;      // H-result / mu / product stride
constexpr int MRPAD = 76;      // mu rows (74 + 2 pad)
constexpr int QST   = 64;

// shared layout (floats)
constexpr int OFF_S1  = 0;                        // 84x92
constexpr int OFF_S2  = OFF_S1  + RROWS * RST;    // 7728
constexpr int OFF_TH1 = OFF_S2  + RROWS * RST;    // 15456 (86x80)
constexpr int OFF_TH2 = OFF_TH1 + THROWS * MST;   // 22336 (86x80)
constexpr int OFF_TH3 = OFF_TH2 + THROWS * MST;   // 29216 (74x80)
constexpr int OFF_M1  = OFF_TH3 + 74 * MST;       // 35136 (76x80)
constexpr int OFF_M2  = OFF_M1  + MRPAD * MST;    // 41216
constexpr int SMEM_FLOATS = OFF_M2 + MRPAD * MST; // 47296 -> 189.2 KB

// Q buffers (H-blurred products) live in the dead s1/s2 region
constexpr int OFF_Q1 = 0;                         // 74x64
constexpr int OFF_Q2 = OFF_Q1 + 74 * QST;         // 4736
constexpr int OFF_Q3 = OFF_Q2 + 74 * QST;         // 9472 (ends 14208 < 15456)
}

__device__ int    g_min_bits = 0x7F800000;
__device__ int    g_max_bits = 0;
__device__ double g_sum = 0.0;

typedef unsigned long long ull;

__device__ __forceinline__ void ffma2(ull& d, ull a, ull b) {
    asm("fma.rn.f32x2 %0, %1, %2, %3;" : "=l"(d) : "l"(a), "l"(b), "l"(d));
}
union F2U { float2 f; ull u; };

// ---------------------------------------------------------------------------
// K0: reset accumulators (first launch; also shifts ncu capture onto k_ssim)
__global__ void k_reset() {
    g_sum = 0.0;
    g_min_bits = 0x7F800000;
    g_max_bits = 0;
}

// ---------------------------------------------------------------------------
__global__ void k_minmax(const float4* __restrict__ a, const float4* __restrict__ b, int n4) {
    float mn = __int_as_float(0x7F800000);
    float mx = 0.f;
    int stride = gridDim.x * blockDim.x;
    for (int i = blockIdx.x * blockDim.x + threadIdx.x; i < n4; i += stride) {
        float4 x = a[i], y = b[i];
        mn = fminf(mn, fminf(fminf(x.x, x.y), fminf(x.z, x.w)));
        mx = fmaxf(mx, fmaxf(fmaxf(x.x, x.y), fmaxf(x.z, x.w)));
        mn = fminf(mn, fminf(fminf(y.x, y.y), fminf(y.z, y.w)));
        mx = fmaxf(mx, fmaxf(fmaxf(y.x, y.y), fmaxf(y.z, y.w)));
    }
    #pragma unroll
    for (int o = 16; o; o >>= 1) {
        mn = fminf(mn, __shfl_xor_sync(0xFFFFFFFFu, mn, o));
        mx = fmaxf(mx, __shfl_xor_sync(0xFFFFFFFFu, mx, o));
    }
    if ((threadIdx.x & 31) == 0) {
        atomicMin(&g_min_bits, __float_as_int(mn));
        atomicMax(&g_max_bits, __float_as_int(mx));
    }
}

// ---------------------------------------------------------------------------
__global__ __launch_bounds__(NT, 1)
void k_ssim(const float* __restrict__ img1, const float* __restrict__ img2,
            const float* __restrict__ kern) {
    extern __shared__ float sm[];
    __shared__ float sw[12];
    __shared__ ull   sw2[12];
    __shared__ float red[NT / 32];

    const int tid = threadIdx.x;
    if (tid < KSZ) {
        float s = 0.f;
        #pragma unroll
        for (int j = 0; j < KSZ; j++) s += kern[tid * KSZ + j];
        sw[tid] = s;
        F2U u; u.f = make_float2(s, s);
        sw2[tid] = u.u;
    }

    const float mnv = __int_as_float(g_min_bits);
    const float mxv = __int_as_float(g_max_bits);
    const float vr = mxv - mnv + 1e-5f;
    float C1 = 0.01f * vr; C1 *= C1;
    float C2 = 0.03f * vr; C2 *= C2;

    const int bx = blockIdx.x, by = blockIdx.y, bz = blockIdx.z;
    const float* i1 = img1 + (size_t)bz * (IMG * IMG);
    const float* i2 = img2 + (size_t)bz * (IMG * IMG);
    const int y0 = by * T - 10;
    const int x0 = bx * T - 10;

    float* s1  = sm + OFF_S1;
    float* s2  = sm + OFF_S2;
    float* tH1 = sm + OFF_TH1;
    float* tH2 = sm + OFF_TH2;
    float* tH3 = sm + OFF_TH3;
    float* m1  = sm + OFF_M1;
    float* m2  = sm + OFF_M2;

    // ---- P0: load tiles (zero-pad outside the image) --------------------
    for (int i = tid; i < 2 * RROWS * RST; i += NT) {
        int img = i >= RROWS * RST;
        int t2 = i - img * RROWS * RST;
        int r = t2 / RST, c = t2 - r * RST;
        int gy = y0 + r, gx = x0 + c;
        bool in = (gy >= 0 && gy < IMG && gx >= 0 && gx < IMG);
        int gi = gy * IMG + gx;
        (img ? s2 : s1)[t2] = in ? (img ? i2 : i1)[gi] : 0.f;
    }
    __syncthreads();

    // ---- P1: H-blur both images, 8-wide groups (84 x 10 x 2 = 1680) -----
    for (int it = tid; it < 2 * RROWS * 10; it += NT) {
        int img = it >= RROWS * 10;
        int t2 = it - img * RROWS * 10;
        int row = t2 / 10, c8 = (t2 - row * 10) * 8;
        const float* src = (img ? s2 : s1) + row * RST + c8;
        float vf[20];
        #pragma unroll
        for (int q = 0; q < 5; q++) {
            float4 v = *(const float4*)(src + 4 * q);
            vf[4*q] = v.x; vf[4*q+1] = v.y; vf[4*q+2] = v.z; vf[4*q+3] = v.w;
        }
        float a[8];
        #pragma unroll
        for (int j = 0; j < 8; j++) a[j] = 0.f;
        #pragma unroll
        for (int k = 0; k < KSZ; k++) {
            float w = sw[k];
            #pragma unroll
            for (int j = 0; j < 8; j++) a[j] = fmaf(w, vf[k + j], a[j]);
        }
        float* dst = (img ? tH2 : tH1) + row * MST + c8;
        *(float4*)dst       = make_float4(a[0], a[1], a[2], a[3]);
        *(float4*)(dst + 4) = make_float4(a[4], a[5], a[6], a[7]);
    }
    __syncthreads();

    // ---- P2: V-blur -> mu, 4row x 4col streamed (19 x 19 x 2 = 722) -----
    for (int it = tid; it < 2 * 19 * 19; it += NT) {
        int img = it >= 19 * 19;
        int t2 = it - img * 19 * 19;
        int rg = t2 / 19, c4 = (t2 - rg * 19) * 4;
        int r4 = rg * 4;
        const float* src = (img ? tH2 : tH1) + r4 * MST + c4;
        ull acc[4][2];
        #pragma unroll
        for (int r = 0; r < 4; r++) { acc[r][0] = 0; acc[r][1] = 0; }
        #pragma unroll
        for (int k = 0; k < 14; k++) {
            ulonglong2 q = *(const ulonglong2*)(src + k * MST);
            #pragma unroll
            for (int r = 0; r < 4; r++) {
                int t = k - r;
                if (t >= 0 && t < KSZ) {
                    ull wk = sw2[t];
                    ffma2(acc[r][0], wk, q.x);
                    ffma2(acc[r][1], wk, q.y);
                }
            }
        }
        float* dst = (img ? m2 : m1) + r4 * MST + c4;
        #pragma unroll
        for (int r = 0; r < 4; r++)
            *(ulonglong2*)(dst + r * MST) = make_ulonglong2(acc[r][0], acc[r][1]);
    }
    __syncthreads();

    // ---- P3: products, zeroed outside image (74 x 74) -------------------
    {
        int my0 = y0 + 5, mx0 = x0 + 5;
        for (int i = tid; i < 74 * 74; i += NT) {
            int r = i / 74, c = i - r * 74;
            int gy = my0 + r, gx = mx0 + c;
            bool in = (gy >= 0 && gy < IMG && gx >= 0 && gx < IMG);
            int mi = r * MST + c;
            float d1 = s1[(r + 5) * RST + (c + 5)] - m1[mi];
            float d2 = s2[(r + 5) * RST + (c + 5)] - m2[mi];
            tH1[mi] = in ? d1 * d1 : 0.f;
            tH2[mi] = in ? d2 * d2 : 0.f;
            tH3[mi] = in ? d1 * d2 : 0.f;
        }
    }
    __syncthreads();

    // ---- P4: H-blur 3 products, 8-wide (74 x 8 x 3 = 1776) --------------
    for (int it = tid; it < 3 * 74 * 8; it += NT) {
        int p = it / (74 * 8);
        int t2 = it - p * (74 * 8);
        int row = t2 / 8, c8 = (t2 - row * 8) * 8;
        const float* src = (p == 0 ? tH1 : (p == 1 ? tH2 : tH3)) + row * MST + c8;
        float vf[20];
        #pragma unroll
        for (int q = 0; q < 5; q++) {
            float4 v = *(const float4*)(src + 4 * q);
            vf[4*q] = v.x; vf[4*q+1] = v.y; vf[4*q+2] = v.z; vf[4*q+3] = v.w;
        }
        float a[8];
        #pragma unroll
        for (int j = 0; j < 8; j++) a[j] = 0.f;
        #pragma unroll
        for (int k = 0; k < KSZ; k++) {
            float w = sw[k];
            #pragma unroll
            for (int j = 0; j < 8; j++) a[j] = fmaf(w, vf[k + j], a[j]);
        }
        float* dst = sm + (p == 0 ? OFF_Q1 : (p == 1 ? OFF_Q2 : OFF_Q3)) + row * QST + c8;
        *(float4*)dst       = make_float4(a[0], a[1], a[2], a[3]);
        *(float4*)(dst + 4) = make_float4(a[4], a[5], a[6], a[7]);
    }
    __syncthreads();

    // ---- P5: fused V-blur of products + combine -------------------------
    // 4-row x 2-col items: 16 rowgroups x 32 colgroups = 512 (exactly NT)
    float acc = 0.f;
    {
        int rg = tid / 32, cg = tid - rg * 32;
        int r4 = rg * 4, c2 = cg * 2;
        ull s11[4], s22[4], s12[4];
        #pragma unroll
        for (int p = 0; p < 3; p++) {
            const ull* src = (const ull*)(sm + (p == 0 ? OFF_Q1 : (p == 1 ? OFF_Q2 : OFF_Q3))
                                          + r4 * QST + c2);
            ull a0 = 0, a1 = 0, a2 = 0, a3 = 0;
            #pragma unroll
            for (int k = 0; k < 14; k++) {
                ull q = src[k * (QST / 2)];
                if (k < 11)           ffma2(a0, sw2[k], q);
                if (k >= 1 && k < 12) ffma2(a1, sw2[k - 1], q);
                if (k >= 2 && k < 13) ffma2(a2, sw2[k - 2], q);
                if (k >= 3)           ffma2(a3, sw2[k - 3], q);
            }
            ull* dst = (p == 0 ? s11 : (p == 1 ? s22 : s12));
            dst[0] = a0; dst[1] = a1; dst[2] = a2; dst[3] = a3;
        }
        #pragma unroll
        for (int i = 0; i < 4; i++) {
            F2U u11, u22, u12;
            u11.u = s11[i]; u22.u = s22[i]; u12.u = s12[i];
            const float a11[2] = {u11.f.x, u11.f.y};
            const float a22[2] = {u22.f.x, u22.f.y};
            const float a12[2] = {u12.f.x, u12.f.y};
            #pragma unroll
            for (int j = 0; j < 2; j++) {
                float u1 = m1[(r4 + 5 + i) * MST + (c2 + 5 + j)];
                float u2 = m2[(r4 + 5 + i) * MST + (c2 + 5 + j)];
                float a = a11[j] + 1.f;
                float b = a22[j] + 1.f;
                float c = a12[j] + 1.f;
                float m11 = u1 * u1 + 1.f;
                float m22 = u2 * u2 + 1.f;
                float m12 = u1 * u2 + 1.f;
                float t2v = 2.f * m12;
                float t1v = m11 + m22;
                float num = (2.f * c + C2) * (t2v * t2v + C1);
                float den = (a + b + C2) * (t1v * t1v + C1);
                acc += __fdividef(num, den);
            }
        }
    }
    #pragma unroll
    for (int o = 16; o; o >>= 1) acc += __shfl_xor_sync(0xFFFFFFFFu, acc, o);
    if ((tid & 31) == 0) red[tid >> 5] = acc;
    __syncthreads();
    if (tid < 32) {
        float v = (tid < NT / 32) ? red[tid] : 0.f;
        #pragma unroll
        for (int o = 16; o; o >>= 1) v += __shfl_xor_sync(0xFFFFFFFFu, v, o);
        if (tid == 0) atomicAdd(&g_sum, (double)v);
    }
}

// ---------------------------------------------------------------------------
__global__ void k_final(float* __restrict__ out) {
    out[0] = 1.0f - (float)(g_sum * (1.0 / (double)NPIX));
}

// ---------------------------------------------------------------------------
extern "C" void kernel_launch(void* const* d_in, const int* in_sizes, int n_in,
                              void* d_out, int out_size) {
    const float* img1 = (const float*)d_in[0];
    const float* img2 = (const float*)d_in[1];
    const float* kern = (const float*)d_in[2];
    float* out = (float*)d_out;

    cudaFuncSetAttribute(k_ssim, cudaFuncAttributeMaxDynamicSharedMemorySize,
                         SMEM_FLOATS * (int)sizeof(float));

    k_reset<<<1, 1>>>();
    k_minmax<<<1024, 256>>>((const float4*)img1, (const float4*)img2,
                            (int)(NPIX / 4));
    dim3 grid(IMG / T, IMG / T, 16);
    k_ssim<<<grid, NT, SMEM_FLOATS * (int)sizeof(float)>>>(img1, img2, kern);
    k_final<<<1, 1>>>(out);
}